// round 15
// baseline (speedup 1.0000x reference)
#include <cuda_runtime.h>
#include <cuda_fp16.h>

typedef unsigned long long ull;

// Problem constants (fixed by the dataset)
#define BB 32
#define NN 200
#define DD 100
#define IT 16             // i-rows per block (two 8-row groups)
#define DPAD 104          // padded d rows in htd
#define JPAD 208          // padded j cols in htd / pp (13 k16 tiles)
#define PTS 17            // pt row stride (floats): odd -> conflict-free column reads
#define PPS 216           // pp row stride (halves)
#define NEGV (-9e15f)

// smem (floats): gf(fp16) | pt(f32) | pp(fp16)
#define OFF_PT  3584                         // gf: 4*7*32*8 halves = 3584 floats
#define OFF_PP  (OFF_PT + NN*PTS)            // pt: 3400 floats
#define SMEM_FLOATS (OFF_PP + (16*PPS)/2)    // pp: 3456 halves = 1728 floats
#define SMEM_BYTES  (SMEM_FLOATS*4)          // 34848 B

// Fragment-native permuted h: sB[b][j][128 halves]
//   offset o = tig*32 + ks*4 + hi*2 + e  <->  d = 16*ks + 2*tig + 8*hi + e
__device__ __align__(16) __half sB_scratch[(size_t)BB * NN * 128];
// Edge weights in the same permuted layout: ahp[k][128 halves]
__device__ __align__(16) __half ahp_scratch[4 * 128];
// fp16 d-major embeddings for agg B-fragments: htd[b][d][j]
__device__ __align__(16) __half htd_scratch[(size_t)BB * DPAD * JPAD];

// ---- fused prep: gather emb -> sB (permuted) + htd (d-major) + ahp ----
__global__ __launch_bounds__(256)
void prep_kernel(const int* __restrict__ inputs,
                 const float* __restrict__ emb,
                 const float* __restrict__ a0,
                 const float* __restrict__ a1,
                 const float* __restrict__ a2,
                 const float* __restrict__ a3)
{
    __shared__ __half th[112][26];   // [d][r], r = j within this block's group
    const int jg   = blockIdx.x;
    const int b    = blockIdx.y;
    const int tid  = threadIdx.x;
    const int w    = tid >> 5;
    const int lane = tid & 31;

    if (jg == 8) {
        // zero-pad htd columns j = 200..207 (all d)
        for (int u = tid; u < DPAD * 8; u += 256) {
            int d = u >> 3, jj = NN + (u & 7);
            htd_scratch[((size_t)b * DPAD + d) * JPAD + jj] = __float2half(0.f);
        }
        // ahp staging (once per grid: use b==0 tail block)
        if (b == 0) {
            int k = tid >> 6, s = tid & 63;
            int o = 2 * s;
            int tg = o >> 5, ks = (o >> 2) & 7, hi = (o >> 1) & 1;
            int d = 16 * ks + 2 * tg + 8 * hi;
            const float* ak = (k == 0) ? a0 : (k == 1) ? a1 : (k == 2) ? a2 : a3;
            __half2 v;
            v.x = __float2half((d     < DD) ? ak[d]     : 0.f);
            v.y = __float2half((d + 1 < DD) ? ak[d + 1] : 0.f);
            *(__half2*)(ahp_scratch + k * 128 + o) = v;
        }
        return;
    }

    // zero the tile (covers d >= 100 padding)
    for (int u = tid; u < (112 * 26) / 2; u += 256)
        ((unsigned*)th)[u] = 0u;
    __syncthreads();

    const int j0 = jg * 25;
    for (int r = w; r < 25; r += 8) {
        int j = j0 + r;
        int id = inputs[b * NN + j];
        if (lane < 25) {
            float4 v = *(const float4*)(emb + (size_t)id * DD + 4 * lane);
            int d = 4 * lane;
            th[d][r]     = __float2half(v.x);
            th[d + 1][r] = __float2half(v.y);
            th[d + 2][r] = __float2half(v.z);
            th[d + 3][r] = __float2half(v.w);
        }
    }
    __syncthreads();

    // sB: permuted rows (coalesced u32 writes)
    for (int u = tid; u < 25 * 64; u += 256) {
        int r = u >> 6, s = u & 63;
        int o = 2 * s;
        int tg = o >> 5, ks = (o >> 2) & 7, hi = (o >> 1) & 1;
        int d = 16 * ks + 2 * tg + 8 * hi;
        __half2 v;
        v.x = (d     < 112) ? th[d][r]     : __float2half(0.f);
        v.y = (d + 1 < 112) ? th[d + 1][r] : __float2half(0.f);
        *(__half2*)(sB_scratch + ((size_t)b * NN + j0 + r) * 128 + o) = v;
    }

    // htd: warp w writes rows d = w, w+8, ... (25 halves contiguous per row)
    for (int d = w; d < DPAD; d += 8) {
        if (lane < 25)
            htd_scratch[((size_t)b * DPAD + d) * JPAD + j0 + lane] = th[d][lane];
    }
}

__global__ __launch_bounds__(256, 3)
void gnn_agg_kernel(const int* __restrict__ adj,
                    float* __restrict__ out)
{
    extern __shared__ float sm[];
    __half* gf = (__half*)sm;             // A frags: [(t4id*7+ks)*32+lane][8 halves]
    float*  pt = sm + OFF_PT;             // [NN][PTS] (first 16 used): alpha staging
    __half* pp = (__half*)(sm + OFF_PP);  // [16][PPS]: fp16 softmax weights
    __shared__ int2 kb_s[NN];             // nibbles: .x rows 0-7, .y rows 8-15

    const int b    = blockIdx.y;
    const int i0   = blockIdx.x * IT;
    const int tid  = threadIdx.x;
    const int w    = tid >> 5;
    const int lane = tid & 31;
    const int gid  = lane >> 2;      // 0..7
    const int tig  = lane & 3;       // 0..3

    // ---- kb table: 16 i-rows per j ----
    if (tid < NN) {
        unsigned lo = 0, hi = 0;
        const int* ap = adj + ((size_t)b * NN + i0) * NN + tid;
#pragma unroll
        for (int i = 0; i < IT; ++i) {
            int a = (i0 + i < NN) ? ap[(size_t)i * NN] : 0;
            unsigned valid = (a >= 1 && a <= 4) ? 4u : 0u;
            unsigned ksel = valid ? (unsigned)(a - 1) : 0u;
            unsigned nib = (ksel | valid);
            if (i < 8) lo |= nib << (4 * i);
            else       hi |= nib << (4 * (i - 8));
        }
        kb_s[tid] = make_int2((int)lo, (int)hi);
    }

    // ---- pp tail init: j in [200,208) must be 0 for the agg kt=12 tile ----
    if (tid < 64) {
        int irow = tid >> 2, c = tid & 3;
        *(unsigned*)(pp + irow * PPS + NN + 2 * c) = 0u;
    }

    // ---- stage A fragments for score: 4 tiles (mt = k-pair, ig = i-group) ----
    const __half* sBb = sB_scratch + (size_t)b * NN * 128;
    for (int e = tid; e < 896; e += 256) {
        int t4id = e / 224, rem = e - t4id * 224;
        int ks = rem >> 5, l = rem & 31;
        int g8 = l >> 2, t4 = l & 3;
        int mt = t4id >> 1, ig = t4id & 1;
        int i = i0 + ig * 8 + g8;
        if (i >= NN) i = NN - 1;          // clamp (junk masked by kb)
        int o = t4 * 32 + ks * 4;
        ull hv = *(const ull*)(sBb + (size_t)i * 128 + o);
        ull aa = *(const ull*)(ahp_scratch + (2 * mt) * 128 + o);
        ull ab = *(const ull*)(ahp_scratch + (2 * mt + 1) * 128 + o);
        __half2 h2[2]; *(ull*)h2 = hv;
        __half2 av[2]; *(ull*)av = aa;
        __half2 bv[2]; *(ull*)bv = ab;
        __half2 pk[4];
        pk[0] = __hmul2(h2[0], av[0]);   // row g8   (k=2mt),   cols lo
        pk[1] = __hmul2(h2[0], bv[0]);   // row g8+8 (k=2mt+1), cols lo
        pk[2] = __hmul2(h2[1], av[1]);   // row g8,   cols hi
        pk[3] = __hmul2(h2[1], bv[1]);   // row g8+8, cols hi
        *(uint4*)(gf + (size_t)(t4id * 7 + ks) * 32 * 8 + l * 8) = *(uint4*)pk;
    }
    __syncthreads();

    // ---- score via HMMA: warp owns tile t4id = w&3, nt stride 2 ----
    const int t4id = w & 3;
    const int mt = t4id >> 1;
    const int ig = t4id & 1;
    unsigned aF[7][4];
#pragma unroll
    for (int ks = 0; ks < 7; ++ks)
        *(uint4*)aF[ks] = *(const uint4*)(gf + (size_t)(t4id * 7 + ks) * 32 * 8 + lane * 8);

    for (int nt = (w >> 2); nt < 25; nt += 2) {
        int jB = nt * 8 + gid;
        const __half* bp = sBb + (size_t)jB * 128 + tig * 32;
        uint4 Bv0 = *(const uint4*)(bp);        // ks0 (x,y), ks1 (z,w)
        uint4 Bv1 = *(const uint4*)(bp + 8);    // ks2, ks3
        uint4 Bv2 = *(const uint4*)(bp + 16);   // ks4, ks5
        uint4 Bv3 = *(const uint4*)(bp + 24);   // ks6, (pad)
        float cA0 = 0.f, cA1 = 0.f, cA2 = 0.f, cA3 = 0.f;
        float cB0 = 0.f, cB1 = 0.f, cB2 = 0.f, cB3 = 0.f;
#define SMMA(acc0, acc1, acc2, acc3, ks, rb0, rb1)                              \
        asm("mma.sync.aligned.m16n8k16.row.col.f32.f16.f16.f32 "                \
            "{%0,%1,%2,%3}, {%4,%5,%6,%7}, {%8,%9}, {%0,%1,%2,%3};"             \
            : "+f"(acc0), "+f"(acc1), "+f"(acc2), "+f"(acc3)                    \
            : "r"(aF[ks][0]), "r"(aF[ks][1]), "r"(aF[ks][2]), "r"(aF[ks][3]),   \
              "r"(rb0), "r"(rb1))
        SMMA(cA0, cA1, cA2, cA3, 0, Bv0.x, Bv0.y);
        SMMA(cA0, cA1, cA2, cA3, 2, Bv1.x, Bv1.y);
        SMMA(cA0, cA1, cA2, cA3, 4, Bv2.x, Bv2.y);
        SMMA(cA0, cA1, cA2, cA3, 6, Bv3.x, Bv3.y);
        SMMA(cB0, cB1, cB2, cB3, 1, Bv0.z, Bv0.w);
        SMMA(cB0, cB1, cB2, cB3, 3, Bv1.z, Bv1.w);
        SMMA(cB0, cB1, cB2, cB3, 5, Bv2.z, Bv2.w);
#undef SMMA
        float c0 = cA0 + cB0, c1 = cA1 + cB1;
        float c2 = cA2 + cB2, c3 = cA3 + cB3;
        // epilogue: every cell written exactly once across mt0/mt1 warps
        int j0 = nt * 8 + tig * 2;
        int2 kv0 = kb_s[j0];
        int2 kv1 = kb_s[j0 + 1];
        unsigned k0 = (unsigned)(ig ? kv0.y : kv0.x) >> (4 * gid);
        unsigned k1 = (unsigned)(ig ? kv1.y : kv1.x) >> (4 * gid);
        int iloc = ig * 8 + gid;
        float v0 = (c0 >= 0.f) ? c0 : 0.2f * c0;   // k = 2mt,   j0
        float v1 = (c1 >= 0.f) ? c1 : 0.2f * c1;   // k = 2mt,   j0+1
        float v2 = (c2 >= 0.f) ? c2 : 0.2f * c2;   // k = 2mt+1, j0
        float v3 = (c3 >= 0.f) ? c3 : 0.2f * c3;   // k = 2mt+1, j0+1
        unsigned kk0 = k0 & 3u, kk1 = k1 & 3u;
        bool val0 = (k0 & 4u) != 0, val1 = (k1 & 4u) != 0;
        if (mt == 0) {
            float r0 = !val0 ? NEGV : (kk0 == 0 ? v0 : v2);
            if (!val0 || kk0 <= 1) pt[j0 * PTS + iloc] = r0;
            float r1 = !val1 ? NEGV : (kk1 == 0 ? v1 : v3);
            if (!val1 || kk1 <= 1) pt[(j0 + 1) * PTS + iloc] = r1;
        } else {
            if (val0 && kk0 >= 2) pt[j0 * PTS + iloc]       = (kk0 == 2 ? v0 : v2);
            if (val1 && kk1 >= 2) pt[(j0 + 1) * PTS + iloc] = (kk1 == 2 ? v1 : v3);
        }
    }
    __syncthreads();

    // ---- softmax: warp w owns rows 2w and 2w+1 ----
#pragma unroll
    for (int r = 0; r < 2; ++r) {
        int irow = 2 * w + r;
        float al[7];
#pragma unroll
        for (int t = 0; t < 7; ++t) {
            int jj = lane + 32 * t;
            al[t] = (jj < NN) ? pt[jj * PTS + irow] : NEGV;
        }
        float m = al[0];
#pragma unroll
        for (int t = 1; t < 7; ++t) m = fmaxf(m, al[t]);
#pragma unroll
        for (int off = 16; off > 0; off >>= 1)
            m = fmaxf(m, __shfl_xor_sync(0xffffffffu, m, off));

        float pv[7];
        float sum = 0.f;
#pragma unroll
        for (int t = 0; t < 7; ++t) {
            int jj = lane + 32 * t;
            float e = (jj < NN) ? __expf(al[t] - m) : 0.f;
            pv[t] = e;
            sum += e;
        }
#pragma unroll
        for (int off = 16; off > 0; off >>= 1)
            sum += __shfl_xor_sync(0xffffffffu, sum, off);
        float rinv = 1.f / sum;
#pragma unroll
        for (int t = 0; t < 7; ++t) {
            int jj = lane + 32 * t;
            if (jj < NN) pp[irow * PPS + jj] = __float2half(pv[t] * rinv);
        }
    }
    __syncthreads();

    // ---- aggregation via HMMA: warps 0-3 -> i-group 0, warps 4-7 -> i-group 1 ----
    {
        const int aig = w >> 2;
        const int nt0 = w & 3;
        unsigned pA0[13], pA1[13];
#pragma unroll
        for (int kt = 0; kt < 13; ++kt) {
            pA0[kt] = *(const unsigned*)(pp + (aig * 8 + gid) * PPS + kt * 16 + tig * 2);
            pA1[kt] = *(const unsigned*)(pp + (aig * 8 + gid) * PPS + kt * 16 + tig * 2 + 8);
        }

        for (int nt = nt0; nt < 13; nt += 4) {
            const __half* hb = htd_scratch + ((size_t)b * DPAD + nt * 8 + gid) * JPAD + tig * 2;
            unsigned hb0[13], hb1[13];
#pragma unroll
            for (int kt = 0; kt < 13; ++kt) {
                hb0[kt] = *(const unsigned*)(hb + kt * 16);
                hb1[kt] = *(const unsigned*)(hb + kt * 16 + 8);
            }
            float cA0 = 0.f, cA1 = 0.f, cA2 = 0.f, cA3 = 0.f;
            float cB0 = 0.f, cB1 = 0.f, cB2 = 0.f, cB3 = 0.f;
#pragma unroll
            for (int kt = 0; kt < 13; kt += 2) {
                asm("mma.sync.aligned.m16n8k16.row.col.f32.f16.f16.f32 "
                    "{%0,%1,%2,%3}, {%4,%5,%6,%7}, {%8,%9}, {%0,%1,%2,%3};"
                    : "+f"(cA0), "+f"(cA1), "+f"(cA2), "+f"(cA3)
                    : "r"(pA0[kt]), "r"(0u), "r"(pA1[kt]), "r"(0u),
                      "r"(hb0[kt]), "r"(hb1[kt]));
            }
#pragma unroll
            for (int kt = 1; kt < 13; kt += 2) {
                asm("mma.sync.aligned.m16n8k16.row.col.f32.f16.f16.f32 "
                    "{%0,%1,%2,%3}, {%4,%5,%6,%7}, {%8,%9}, {%0,%1,%2,%3};"
                    : "+f"(cB0), "+f"(cB1), "+f"(cB2), "+f"(cB3)
                    : "r"(pA0[kt]), "r"(0u), "r"(pA1[kt]), "r"(0u),
                      "r"(hb0[kt]), "r"(hb1[kt]));
            }
            int d0 = nt * 8 + tig * 2;
            int orow = i0 + aig * 8 + gid;
            if (d0 < DD && orow < NN) {
                float2 o;
                o.x = cA0 + cB0;
                o.y = cA1 + cB1;
                *(float2*)(out + (size_t)(b * NN + orow) * DD + d0) = o;
            }
        }
    }
}

extern "C" void kernel_launch(void* const* d_in, const int* in_sizes, int n_in,
                              void* d_out, int out_size)
{
    const int*   inputs = (const int*)d_in[0];
    const int*   adj    = (const int*)d_in[1];
    // d_in[2] = mask_item (unused by reference)
    const float* emb    = (const float*)d_in[3];
    const float* a0     = (const float*)d_in[4];
    const float* a1     = (const float*)d_in[5];
    const float* a2     = (const float*)d_in[6];
    const float* a3     = (const float*)d_in[7];
    float*       out    = (float*)d_out;

    cudaFuncSetAttribute(gnn_agg_kernel,
                         cudaFuncAttributeMaxDynamicSharedMemorySize,
                         SMEM_BYTES);

    // Phase 1: fused gather + permuted fp16 layouts (sB, htd, ahp)
    dim3 pg(9, BB);      // 9 x 32 = 288 blocks
    prep_kernel<<<pg, 256>>>(inputs, emb, a0, a1, a2, a3);

    // Phase 2: fused HMMA-score / softmax / HMMA-aggregate
    dim3 grid((NN + IT - 1) / IT, BB);   // 13 x 32 = 416 blocks (~1 wave at 3/SM)
    gnn_agg_kernel<<<grid, 256, SMEM_BYTES>>>(adj, out);
}

// round 16
// speedup vs baseline: 1.2675x; 1.2675x over previous
#include <cuda_runtime.h>
#include <cuda_fp16.h>

typedef unsigned long long ull;

// Problem constants (fixed by the dataset)
#define BB 32
#define NN 200
#define DD 100
#define IT 16             // i-rows per block (two 8-row groups)
#define DPAD 104          // padded d rows in htd
#define JPAD 208          // padded j cols in htd / pp (13 k16 tiles)
#define PTS 17            // pt row stride (floats): odd -> conflict-free column reads
#define PPS 216           // pp row stride (halves)
#define NEGV (-9e15f)

// smem (floats): gf(fp16) | pt(f32) | pp(fp16)
#define OFF_PT  3584                         // gf: 4*7*32*8 halves = 3584 floats
#define OFF_PP  (OFF_PT + NN*PTS)            // pt: 3400 floats
#define SMEM_FLOATS (OFF_PP + (16*PPS)/2)    // pp: 3456 halves = 1728 floats
#define SMEM_BYTES  (SMEM_FLOATS*4)          // 34848 B

// Tile-blocked fragment-native h for score B:
//   sBt[b][nt][l][lane][8 halves], l = ks-pair chunk (ks 2l, 2l+1)
//   lane (gid,t4): x = (ks=2l, d=32l+2t4+{0,1}), y = (+8), z/w = ks=2l+1
__device__ __align__(16) __half sBt_scratch[(size_t)BB * 25 * 4 * 32 * 8];
// Edge weights, same chunk convention: ahq[k][l][t4][8 halves]
__device__ __align__(16) __half ahq_scratch[4 * 4 * 4 * 8];
// fp16 d-major embeddings for agg B-fragments: htd[b][d][j]
__device__ __align__(16) __half htd_scratch[(size_t)BB * DPAD * JPAD];

__device__ __forceinline__ __half2 u2h2(unsigned u) {
    __half2 h; *(unsigned*)&h = u; return h;
}
__device__ __forceinline__ unsigned h22u(__half2 h) {
    return *(unsigned*)&h;
}

// ---- fused prep: gather emb -> sBt (tile-blocked) + htd (d-major) + ahq ----
// grid (6, BB): jg=0..4 own 40 j (5 score tiles) each; jg==5 = pads + ahq
__global__ __launch_bounds__(256)
void prep_kernel(const int* __restrict__ inputs,
                 const float* __restrict__ emb,
                 const float* __restrict__ a0,
                 const float* __restrict__ a1,
                 const float* __restrict__ a2,
                 const float* __restrict__ a3)
{
    __shared__ __half th[112][41];   // [d][r], r = j within this block's group
    const int jg   = blockIdx.x;
    const int b    = blockIdx.y;
    const int tid  = threadIdx.x;
    const int w    = tid >> 5;
    const int lane = tid & 31;

    if (jg == 5) {
        // zero-pad htd columns j = 200..207 (all d)
        for (int u = tid; u < DPAD * 8; u += 256) {
            int d = u >> 3, jj = NN + (u & 7);
            htd_scratch[((size_t)b * DPAD + d) * JPAD + jj] = __float2half(0.f);
        }
        // ahq staging (once)
        if (b == 0 && tid < 64) {
            int k = tid >> 4, lq = (tid >> 2) & 3, t4 = tid & 3;
            const float* ak = (k == 0) ? a0 : (k == 1) ? a1 : (k == 2) ? a2 : a3;
            __half hv[8];
            int dA = 32 * lq + 2 * t4;
            int dB = dA + 16;
#pragma unroll
            for (int s = 0; s < 2; ++s) {
                int d0 = dA + 8 * s;
                hv[2*s]   = __float2half((d0     < DD) ? ak[d0]     : 0.f);
                hv[2*s+1] = __float2half((d0 + 1 < DD) ? ak[d0 + 1] : 0.f);
                int d1 = dB + 8 * s;
                hv[4+2*s]   = __float2half((d1     < DD) ? ak[d1]     : 0.f);
                hv[4+2*s+1] = __float2half((d1 + 1 < DD) ? ak[d1 + 1] : 0.f);
            }
            *(uint4*)(ahq_scratch + ((k * 4 + lq) * 4 + t4) * 8) = *(uint4*)hv;
        }
        return;
    }

    // zero the tile (covers d >= 100 padding)
    for (int u = tid; u < 112 * 41; u += 256)
        th[u / 41][u % 41] = __float2half(0.f);
    __syncthreads();

    const int j0 = jg * 40;
    for (int r = w; r < 40; r += 8) {
        int j = j0 + r;
        int id = inputs[b * NN + j];
        if (lane < 25) {
            float4 v = *(const float4*)(emb + (size_t)id * DD + 4 * lane);
            int d = 4 * lane;
            th[d][r]     = __float2half(v.x);
            th[d + 1][r] = __float2half(v.y);
            th[d + 2][r] = __float2half(v.z);
            th[d + 3][r] = __float2half(v.w);
        }
    }
    __syncthreads();

    // sBt: 5 tiles x 4 chunks x 32 lanes, coalesced uint4 stores
    for (int e = tid; e < 640; e += 256) {
        int nt_l = e >> 7, rem = e & 127;
        int l = rem >> 5, ln = rem & 31;
        int gid = ln >> 2, t4 = ln & 3;
        int r = nt_l * 8 + gid;
        int dA = 32 * l + 2 * t4;
        int dB = dA + 16;
        __half hv[8];
        hv[0] = th[dA][r];     hv[1] = th[dA + 1][r];
        hv[2] = th[dA + 8][r]; hv[3] = th[dA + 9][r];
        if (dB + 9 < 112) {
            hv[4] = th[dB][r];     hv[5] = th[dB + 1][r];
            hv[6] = th[dB + 8][r]; hv[7] = th[dB + 9][r];
        } else {
            hv[4] = hv[5] = hv[6] = hv[7] = __float2half(0.f);  // ks7 pad
        }
        int nt = jg * 5 + nt_l;
        *(uint4*)(sBt_scratch + ((((size_t)b * 25 + nt) * 4 + l) * 32 + ln) * 8) = *(uint4*)hv;
    }

    // htd: warp w writes rows d = w, w+8, ... (40 halves contiguous per row)
    for (int d = w; d < DPAD; d += 8) {
        if (lane < 20) {
            __half2 v = __halves2half2(th[d][2 * lane], th[d][2 * lane + 1]);
            *(__half2*)(htd_scratch + ((size_t)b * DPAD + d) * JPAD + j0 + 2 * lane) = v;
        }
    }
}

__global__ __launch_bounds__(256, 3)
void gnn_agg_kernel(const int* __restrict__ adj,
                    float* __restrict__ out)
{
    extern __shared__ float sm[];
    __half* gf = (__half*)sm;             // A frags: [(t4id*7+ks)*32+lane][8 halves]
    float*  pt = sm + OFF_PT;             // [NN][PTS] (first 16 used): alpha staging
    __half* pp = (__half*)(sm + OFF_PP);  // [16][PPS]: fp16 softmax weights
    __shared__ int2 kb_s[NN];             // nibbles: .x rows 0-7, .y rows 8-15

    const int b    = blockIdx.y;
    const int i0   = blockIdx.x * IT;
    const int tid  = threadIdx.x;
    const int w    = tid >> 5;
    const int lane = tid & 31;
    const int gid  = lane >> 2;      // 0..7
    const int tig  = lane & 3;       // 0..3

    // ---- kb table: 16 i-rows per j ----
    if (tid < NN) {
        unsigned lo = 0, hi = 0;
        const int* ap = adj + ((size_t)b * NN + i0) * NN + tid;
#pragma unroll
        for (int i = 0; i < IT; ++i) {
            int a = (i0 + i < NN) ? ap[(size_t)i * NN] : 0;
            unsigned valid = (a >= 1 && a <= 4) ? 4u : 0u;
            unsigned ksel = valid ? (unsigned)(a - 1) : 0u;
            unsigned nib = (ksel | valid);
            if (i < 8) lo |= nib << (4 * i);
            else       hi |= nib << (4 * (i - 8));
        }
        kb_s[tid] = make_int2((int)lo, (int)hi);
    }

    // ---- pp tail init: j in [200,208) must be 0 for the agg kt=12 tile ----
    if (tid < 64) {
        int irow = tid >> 2, c = tid & 3;
        *(unsigned*)(pp + irow * PPS + NN + 2 * c) = 0u;
    }

    // ---- stage A fragments for score (reads tile-blocked sBt + ahq) ----
    const __half* sBb = sBt_scratch + (size_t)b * 25 * 4 * 32 * 8;
    for (int e = tid; e < 512; e += 256) {
        int t4id = e >> 7, rem = e & 127;
        int lp = rem >> 5, l = rem & 31;
        int g8 = l >> 2, t4 = l & 3;
        int mt = t4id >> 1, ig = t4id & 1;
        int i = i0 + ig * 8 + g8;
        if (i >= NN) i = NN - 1;          // clamp (junk masked by kb)
        uint4 hv4 = *(const uint4*)(sBb + ((((size_t)(i >> 3)) * 4 + lp) * 32 + (i & 7) * 4 + t4) * 8);
        uint4 aa4 = *(const uint4*)(ahq_scratch + (((2 * mt) * 4 + lp) * 4 + t4) * 8);
        uint4 ab4 = *(const uint4*)(ahq_scratch + (((2 * mt + 1) * 4 + lp) * 4 + t4) * 8);
        // ksA = 2lp
        {
            __half2 pk[4];
            pk[0] = __hmul2(u2h2(hv4.x), u2h2(aa4.x));   // row g8   (k=2mt),   cols lo
            pk[1] = __hmul2(u2h2(hv4.x), u2h2(ab4.x));   // row g8+8 (k=2mt+1), cols lo
            pk[2] = __hmul2(u2h2(hv4.y), u2h2(aa4.y));   // row g8,   cols hi
            pk[3] = __hmul2(u2h2(hv4.y), u2h2(ab4.y));   // row g8+8, cols hi
            *(uint4*)(gf + (size_t)(t4id * 7 + 2 * lp) * 32 * 8 + l * 8) = *(uint4*)pk;
        }
        // ksB = 2lp+1 (skip ks 7)
        if (lp < 3) {
            __half2 pk[4];
            pk[0] = __hmul2(u2h2(hv4.z), u2h2(aa4.z));
            pk[1] = __hmul2(u2h2(hv4.z), u2h2(ab4.z));
            pk[2] = __hmul2(u2h2(hv4.w), u2h2(aa4.w));
            pk[3] = __hmul2(u2h2(hv4.w), u2h2(ab4.w));
            *(uint4*)(gf + (size_t)(t4id * 7 + 2 * lp + 1) * 32 * 8 + l * 8) = *(uint4*)pk;
        }
    }
    __syncthreads();

    // ---- score via HMMA: warp owns tile t4id = w&3, nt stride 2 ----
    const int t4id = w & 3;
    const int mt = t4id >> 1;
    const int ig = t4id & 1;
    unsigned aF[7][4];
#pragma unroll
    for (int ks = 0; ks < 7; ++ks)
        *(uint4*)aF[ks] = *(const uint4*)(gf + (size_t)(t4id * 7 + ks) * 32 * 8 + lane * 8);

    for (int nt = (w >> 2); nt < 25; nt += 2) {
        const __half* bp = sBb + ((size_t)nt * 4 * 32 + lane) * 8;
        uint4 Bv0 = *(const uint4*)(bp);              // ks0 (x,y), ks1 (z,w)
        uint4 Bv1 = *(const uint4*)(bp + 32 * 8);     // ks2, ks3
        uint4 Bv2 = *(const uint4*)(bp + 64 * 8);     // ks4, ks5
        uint4 Bv3 = *(const uint4*)(bp + 96 * 8);     // ks6, pad
        float cA0 = 0.f, cA1 = 0.f, cA2 = 0.f, cA3 = 0.f;
        float cB0 = 0.f, cB1 = 0.f, cB2 = 0.f, cB3 = 0.f;
#define SMMA(acc0, acc1, acc2, acc3, ks, rb0, rb1)                              \
        asm("mma.sync.aligned.m16n8k16.row.col.f32.f16.f16.f32 "                \
            "{%0,%1,%2,%3}, {%4,%5,%6,%7}, {%8,%9}, {%0,%1,%2,%3};"             \
            : "+f"(acc0), "+f"(acc1), "+f"(acc2), "+f"(acc3)                    \
            : "r"(aF[ks][0]), "r"(aF[ks][1]), "r"(aF[ks][2]), "r"(aF[ks][3]),   \
              "r"(rb0), "r"(rb1))
        SMMA(cA0, cA1, cA2, cA3, 0, Bv0.x, Bv0.y);
        SMMA(cA0, cA1, cA2, cA3, 2, Bv1.x, Bv1.y);
        SMMA(cA0, cA1, cA2, cA3, 4, Bv2.x, Bv2.y);
        SMMA(cA0, cA1, cA2, cA3, 6, Bv3.x, Bv3.y);
        SMMA(cB0, cB1, cB2, cB3, 1, Bv0.z, Bv0.w);
        SMMA(cB0, cB1, cB2, cB3, 3, Bv1.z, Bv1.w);
        SMMA(cB0, cB1, cB2, cB3, 5, Bv2.z, Bv2.w);
#undef SMMA
        float c0 = cA0 + cB0, c1 = cA1 + cB1;
        float c2 = cA2 + cB2, c3 = cA3 + cB3;
        // epilogue: every pt cell written exactly once across mt0/mt1 warps
        int j0 = nt * 8 + tig * 2;
        int2 kv0 = kb_s[j0];
        int2 kv1 = kb_s[j0 + 1];
        unsigned k0 = (unsigned)(ig ? kv0.y : kv0.x) >> (4 * gid);
        unsigned k1 = (unsigned)(ig ? kv1.y : kv1.x) >> (4 * gid);
        int iloc = ig * 8 + gid;
        float v0 = (c0 >= 0.f) ? c0 : 0.2f * c0;   // k = 2mt,   j0
        float v1 = (c1 >= 0.f) ? c1 : 0.2f * c1;   // k = 2mt,   j0+1
        float v2 = (c2 >= 0.f) ? c2 : 0.2f * c2;   // k = 2mt+1, j0
        float v3 = (c3 >= 0.f) ? c3 : 0.2f * c3;   // k = 2mt+1, j0+1
        unsigned kk0 = k0 & 3u, kk1 = k1 & 3u;
        bool val0 = (k0 & 4u) != 0, val1 = (k1 & 4u) != 0;
        if (mt == 0) {
            float r0 = !val0 ? NEGV : (kk0 == 0 ? v0 : v2);
            if (!val0 || kk0 <= 1) pt[j0 * PTS + iloc] = r0;
            float r1 = !val1 ? NEGV : (kk1 == 0 ? v1 : v3);
            if (!val1 || kk1 <= 1) pt[(j0 + 1) * PTS + iloc] = r1;
        } else {
            if (val0 && kk0 >= 2) pt[j0 * PTS + iloc]       = (kk0 == 2 ? v0 : v2);
            if (val1 && kk1 >= 2) pt[(j0 + 1) * PTS + iloc] = (kk1 == 2 ? v1 : v3);
        }
    }
    __syncthreads();

    // ---- softmax: warp w owns rows 2w and 2w+1 ----
#pragma unroll
    for (int r = 0; r < 2; ++r) {
        int irow = 2 * w + r;
        float al[7];
#pragma unroll
        for (int t = 0; t < 7; ++t) {
            int jj = lane + 32 * t;
            al[t] = (jj < NN) ? pt[jj * PTS + irow] : NEGV;
        }
        float m = al[0];
#pragma unroll
        for (int t = 1; t < 7; ++t) m = fmaxf(m, al[t]);
#pragma unroll
        for (int off = 16; off > 0; off >>= 1)
            m = fmaxf(m, __shfl_xor_sync(0xffffffffu, m, off));

        float pv[7];
        float sum = 0.f;
#pragma unroll
        for (int t = 0; t < 7; ++t) {
            int jj = lane + 32 * t;
            float e = (jj < NN) ? __expf(al[t] - m) : 0.f;
            pv[t] = e;
            sum += e;
        }
#pragma unroll
        for (int off = 16; off > 0; off >>= 1)
            sum += __shfl_xor_sync(0xffffffffu, sum, off);
        float rinv = 1.f / sum;
#pragma unroll
        for (int t = 0; t < 7; ++t) {
            int jj = lane + 32 * t;
            if (jj < NN) pp[irow * PPS + jj] = __float2half(pv[t] * rinv);
        }
    }
    __syncthreads();

    // ---- aggregation via HMMA: warps 0-3 -> i-group 0, warps 4-7 -> i-group 1 ----
    {
        const int aig = w >> 2;
        const int nt0 = w & 3;
        unsigned pA0[13], pA1[13];
#pragma unroll
        for (int kt = 0; kt < 13; ++kt) {
            pA0[kt] = *(const unsigned*)(pp + (aig * 8 + gid) * PPS + kt * 16 + tig * 2);
            pA1[kt] = *(const unsigned*)(pp + (aig * 8 + gid) * PPS + kt * 16 + tig * 2 + 8);
        }

        for (int nt = nt0; nt < 13; nt += 4) {
            const __half* hb = htd_scratch + ((size_t)b * DPAD + nt * 8 + gid) * JPAD + tig * 2;
            unsigned hb0[13], hb1[13];
#pragma unroll
            for (int kt = 0; kt < 13; ++kt) {
                hb0[kt] = *(const unsigned*)(hb + kt * 16);
                hb1[kt] = *(const unsigned*)(hb + kt * 16 + 8);
            }
            float cA0 = 0.f, cA1 = 0.f, cA2 = 0.f, cA3 = 0.f;
            float cB0 = 0.f, cB1 = 0.f, cB2 = 0.f, cB3 = 0.f;
#pragma unroll
            for (int kt = 0; kt < 13; kt += 2) {
                asm("mma.sync.aligned.m16n8k16.row.col.f32.f16.f16.f32 "
                    "{%0,%1,%2,%3}, {%4,%5,%6,%7}, {%8,%9}, {%0,%1,%2,%3};"
                    : "+f"(cA0), "+f"(cA1), "+f"(cA2), "+f"(cA3)
                    : "r"(pA0[kt]), "r"(0u), "r"(pA1[kt]), "r"(0u),
                      "r"(hb0[kt]), "r"(hb1[kt]));
            }
#pragma unroll
            for (int kt = 1; kt < 13; kt += 2) {
                asm("mma.sync.aligned.m16n8k16.row.col.f32.f16.f16.f32 "
                    "{%0,%1,%2,%3}, {%4,%5,%6,%7}, {%8,%9}, {%0,%1,%2,%3};"
                    : "+f"(cB0), "+f"(cB1), "+f"(cB2), "+f"(cB3)
                    : "r"(pA0[kt]), "r"(0u), "r"(pA1[kt]), "r"(0u),
                      "r"(hb0[kt]), "r"(hb1[kt]));
            }
            int d0 = nt * 8 + tig * 2;
            int orow = i0 + aig * 8 + gid;
            if (d0 < DD && orow < NN) {
                float2 o;
                o.x = cA0 + cB0;
                o.y = cA1 + cB1;
                *(float2*)(out + (size_t)(b * NN + orow) * DD + d0) = o;
            }
        }
    }
}

extern "C" void kernel_launch(void* const* d_in, const int* in_sizes, int n_in,
                              void* d_out, int out_size)
{
    const int*   inputs = (const int*)d_in[0];
    const int*   adj    = (const int*)d_in[1];
    // d_in[2] = mask_item (unused by reference)
    const float* emb    = (const float*)d_in[3];
    const float* a0     = (const float*)d_in[4];
    const float* a1     = (const float*)d_in[5];
    const float* a2     = (const float*)d_in[6];
    const float* a3     = (const float*)d_in[7];
    float*       out    = (float*)d_out;

    cudaFuncSetAttribute(gnn_agg_kernel,
                         cudaFuncAttributeMaxDynamicSharedMemorySize,
                         SMEM_BYTES);

    // Phase 1: fused gather + tile-blocked fp16 layouts (sBt, htd, ahq)
    dim3 pg(6, BB);      // 6 x 32 = 192 blocks
    prep_kernel<<<pg, 256>>>(inputs, emb, a0, a1, a2, a3);

    // Phase 2: fused HMMA-score / softmax / HMMA-aggregate
    dim3 grid((NN + IT - 1) / IT, BB);   // 13 x 32 = 416 blocks (~1 wave at 3/SM)
    gnn_agg_kernel<<<grid, 256, SMEM_BYTES>>>(adj, out);
}

// round 17
// speedup vs baseline: 1.6053x; 1.2664x over previous
#include <cuda_runtime.h>
#include <cuda_fp16.h>

typedef unsigned long long ull;

// Problem constants (fixed by the dataset)
#define BB 32
#define NN 200
#define DD 100
#define IT 16             // i-rows per block (two 8-row groups)
#define PTS 17            // pt row stride (floats): odd -> conflict-free column reads
#define PPS 216           // pp row stride (halves)
#define NEGV (-9e15f)

// smem (floats): gf(fp16) | pt(f32) | pp(fp16)
#define OFF_PT  3584                         // gf: 4*7*32*8 halves = 3584 floats
#define OFF_PP  (OFF_PT + NN*PTS)            // pt: 3400 floats
#define SMEM_FLOATS (OFF_PP + (16*PPS)/2)    // pp: 3456 halves = 1728 floats
#define SMEM_BYTES  (SMEM_FLOATS*4)          // 34848 B

// Tile-blocked fragment-native h for score B:
//   sBt[b][nt][l][lane][8 halves], l = ks-pair chunk (ks 2l, 2l+1)
__device__ __align__(16) __half sBt_scratch[(size_t)BB * 25 * 4 * 32 * 8];
// Edge weights, same chunk convention: ahq[k][l][t4][8 halves]
__device__ __align__(16) __half ahq_scratch[4 * 4 * 4 * 8];
// Fragment-native agg B: hAgg[b][ntd(13)][ktp(7)][lane][8 halves]
//   lane(gid,tig): x = h[d=ntd*8+gid][j=2ktp*16+tig*2,+1], y = j+8,+9 (kt even)
//                  z,w = same for kt = 2ktp+1 (ktp=6 odd slot = zero pad)
__device__ __align__(16) __half hAgg_scratch[(size_t)BB * 13 * 7 * 32 * 8];

__device__ __forceinline__ __half2 u2h2(unsigned u) {
    __half2 h; *(unsigned*)&h = u; return h;
}

// ---- fused prep: gather emb -> sBt + hAgg + ahq ----
// grid (13, BB): block kt owns j in [16kt, 16kt+16)
__global__ __launch_bounds__(256)
void prep_kernel(const int* __restrict__ inputs,
                 const float* __restrict__ emb,
                 const float* __restrict__ a0,
                 const float* __restrict__ a1,
                 const float* __restrict__ a2,
                 const float* __restrict__ a3)
{
    __shared__ __half th[112][18];   // [d][r], r = j - 16*kt; stride 18 halves
    const int kt  = blockIdx.x;      // 0..12
    const int b   = blockIdx.y;
    const int tid = threadIdx.x;

    // zero th (covers d>=100 and j>=200 padding)
    for (int u = tid; u < (112 * 18) / 2; u += 256)
        ((unsigned*)th)[u] = 0u;
    __syncthreads();

    const int j0 = kt * 16;
    // gather up to 16 rows x 25 float4 (coalesced per row)
    for (int u = tid; u < 400; u += 256) {
        int r = u / 25, c = u - r * 25;
        int j = j0 + r;
        if (j < NN) {
            int id = inputs[b * NN + j];
            float4 v = *(const float4*)(emb + (size_t)id * DD + 4 * c);
            int d = 4 * c;
            th[d][r]     = __float2half(v.x);
            th[d + 1][r] = __float2half(v.y);
            th[d + 2][r] = __float2half(v.z);
            th[d + 3][r] = __float2half(v.w);
        }
    }
    __syncthreads();

    // sBt: tiles nt = 2kt, 2kt+1 (2 tiles x 4 chunks x 32 lanes = 256 items)
    {
        int e = tid;
        int nt_l = e >> 7, rem = e & 127;
        int l = rem >> 5, ln = rem & 31;
        int gid = ln >> 2, t4 = ln & 3;
        int nt = 2 * kt + nt_l;
        if (nt < 25) {
            int r = nt_l * 8 + gid;
            int dA = 32 * l + 2 * t4;
            int dB = dA + 16;
            __half hv[8];
            hv[0] = th[dA][r];     hv[1] = th[dA + 1][r];
            hv[2] = th[dA + 8][r]; hv[3] = th[dA + 9][r];
            if (dB + 9 < 112) {
                hv[4] = th[dB][r];     hv[5] = th[dB + 1][r];
                hv[6] = th[dB + 8][r]; hv[7] = th[dB + 9][r];
            } else {
                hv[4] = hv[5] = hv[6] = hv[7] = __float2half(0.f);  // ks7 pad
            }
            *(uint4*)(sBt_scratch + ((((size_t)b * 25 + nt) * 4 + l) * 32 + ln) * 8) = *(uint4*)hv;
        }
    }

    // hAgg: 13 ntd x 32 lanes = 416 items; this block fills kt's slot of ktp=kt/2
    for (int u = tid; u < 416; u += 256) {
        int ntd = u >> 5, ln = u & 31;
        int gid = ln >> 2, t4 = ln & 3;
        int d = ntd * 8 + gid;                 // 0..103 (rows 100..103 are zero)
        __half2 h0 = *(const __half2*)&th[d][2 * t4];
        __half2 h1 = *(const __half2*)&th[d][2 * t4 + 8];
        uint2 v;
        v.x = *(unsigned*)&h0;
        v.y = *(unsigned*)&h1;
        size_t base = ((((size_t)b * 13 + ntd) * 7 + (kt >> 1)) * 32 + ln) * 8;
        *(uint2*)(hAgg_scratch + base + (kt & 1) * 4) = v;
        if (kt == 12) {
            uint2 z; z.x = 0u; z.y = 0u;       // pad kt13 (odd slot of ktp 6)
            *(uint2*)(hAgg_scratch + base + 4) = z;
        }
    }

    // ahq staging (once)
    if (kt == 12 && b == 0 && tid < 64) {
        int k = tid >> 4, lq = (tid >> 2) & 3, t4 = tid & 3;
        const float* ak = (k == 0) ? a0 : (k == 1) ? a1 : (k == 2) ? a2 : a3;
        __half hv[8];
        int dA = 32 * lq + 2 * t4;
        int dB = dA + 16;
#pragma unroll
        for (int s = 0; s < 2; ++s) {
            int d0 = dA + 8 * s;
            hv[2*s]   = __float2half((d0     < DD) ? ak[d0]     : 0.f);
            hv[2*s+1] = __float2half((d0 + 1 < DD) ? ak[d0 + 1] : 0.f);
            int d1 = dB + 8 * s;
            hv[4+2*s]   = __float2half((d1     < DD) ? ak[d1]     : 0.f);
            hv[4+2*s+1] = __float2half((d1 + 1 < DD) ? ak[d1 + 1] : 0.f);
        }
        *(uint4*)(ahq_scratch + ((k * 4 + lq) * 4 + t4) * 8) = *(uint4*)hv;
    }
}

__global__ __launch_bounds__(256, 3)
void gnn_agg_kernel(const int* __restrict__ adj,
                    float* __restrict__ out)
{
    extern __shared__ float sm[];
    __half* gf = (__half*)sm;             // A frags: [(t4id*7+ks)*32+lane][8 halves]
    float*  pt = sm + OFF_PT;             // [NN][PTS] (first 16 used): alpha staging
    __half* pp = (__half*)(sm + OFF_PP);  // [16][PPS]: fp16 softmax weights
    __shared__ int2 kb_s[NN];             // nibbles: .x rows 0-7, .y rows 8-15

    const int b    = blockIdx.y;
    const int i0   = blockIdx.x * IT;
    const int tid  = threadIdx.x;
    const int w    = tid >> 5;
    const int lane = tid & 31;
    const int gid  = lane >> 2;      // 0..7
    const int tig  = lane & 3;       // 0..3

    // ---- kb table: 16 i-rows per j ----
    if (tid < NN) {
        unsigned lo = 0, hi = 0;
        const int* ap = adj + ((size_t)b * NN + i0) * NN + tid;
#pragma unroll
        for (int i = 0; i < IT; ++i) {
            int a = (i0 + i < NN) ? ap[(size_t)i * NN] : 0;
            unsigned valid = (a >= 1 && a <= 4) ? 4u : 0u;
            unsigned ksel = valid ? (unsigned)(a - 1) : 0u;
            unsigned nib = (ksel | valid);
            if (i < 8) lo |= nib << (4 * i);
            else       hi |= nib << (4 * (i - 8));
        }
        kb_s[tid] = make_int2((int)lo, (int)hi);
    }

    // ---- pp tail init: j in [200,208) must be 0 for the agg kt=12 tile ----
    if (tid < 64) {
        int irow = tid >> 2, c = tid & 3;
        *(unsigned*)(pp + irow * PPS + NN + 2 * c) = 0u;
    }

    // ---- stage A fragments for score (reads tile-blocked sBt + ahq) ----
    const __half* sBb = sBt_scratch + (size_t)b * 25 * 4 * 32 * 8;
    for (int e = tid; e < 512; e += 256) {
        int t4id = e >> 7, rem = e & 127;
        int lp = rem >> 5, l = rem & 31;
        int g8 = l >> 2, t4 = l & 3;
        int mt = t4id >> 1, ig = t4id & 1;
        int i = i0 + ig * 8 + g8;
        if (i >= NN) i = NN - 1;          // clamp (junk masked by kb)
        uint4 hv4 = *(const uint4*)(sBb + ((((size_t)(i >> 3)) * 4 + lp) * 32 + (i & 7) * 4 + t4) * 8);
        uint4 aa4 = *(const uint4*)(ahq_scratch + (((2 * mt) * 4 + lp) * 4 + t4) * 8);
        uint4 ab4 = *(const uint4*)(ahq_scratch + (((2 * mt + 1) * 4 + lp) * 4 + t4) * 8);
        {
            __half2 pk[4];
            pk[0] = __hmul2(u2h2(hv4.x), u2h2(aa4.x));
            pk[1] = __hmul2(u2h2(hv4.x), u2h2(ab4.x));
            pk[2] = __hmul2(u2h2(hv4.y), u2h2(aa4.y));
            pk[3] = __hmul2(u2h2(hv4.y), u2h2(ab4.y));
            *(uint4*)(gf + (size_t)(t4id * 7 + 2 * lp) * 32 * 8 + l * 8) = *(uint4*)pk;
        }
        if (lp < 3) {
            __half2 pk[4];
            pk[0] = __hmul2(u2h2(hv4.z), u2h2(aa4.z));
            pk[1] = __hmul2(u2h2(hv4.z), u2h2(ab4.z));
            pk[2] = __hmul2(u2h2(hv4.w), u2h2(aa4.w));
            pk[3] = __hmul2(u2h2(hv4.w), u2h2(ab4.w));
            *(uint4*)(gf + (size_t)(t4id * 7 + 2 * lp + 1) * 32 * 8 + l * 8) = *(uint4*)pk;
        }
    }
    __syncthreads();

    // ---- score via HMMA: warp owns tile t4id = w&3, nt stride 2 ----
    const int t4id = w & 3;
    const int mt = t4id >> 1;
    const int ig = t4id & 1;
    unsigned aF[7][4];
#pragma unroll
    for (int ks = 0; ks < 7; ++ks)
        *(uint4*)aF[ks] = *(const uint4*)(gf + (size_t)(t4id * 7 + ks) * 32 * 8 + lane * 8);

    for (int nt = (w >> 2); nt < 25; nt += 2) {
        const __half* bp = sBb + ((size_t)nt * 4 * 32 + lane) * 8;
        uint4 Bv0 = *(const uint4*)(bp);              // ks0 (x,y), ks1 (z,w)
        uint4 Bv1 = *(const uint4*)(bp + 32 * 8);     // ks2, ks3
        uint4 Bv2 = *(const uint4*)(bp + 64 * 8);     // ks4, ks5
        uint4 Bv3 = *(const uint4*)(bp + 96 * 8);     // ks6, pad
        float cA0 = 0.f, cA1 = 0.f, cA2 = 0.f, cA3 = 0.f;
        float cB0 = 0.f, cB1 = 0.f, cB2 = 0.f, cB3 = 0.f;
#define SMMA(acc0, acc1, acc2, acc3, ks, rb0, rb1)                              \
        asm("mma.sync.aligned.m16n8k16.row.col.f32.f16.f16.f32 "                \
            "{%0,%1,%2,%3}, {%4,%5,%6,%7}, {%8,%9}, {%0,%1,%2,%3};"             \
            : "+f"(acc0), "+f"(acc1), "+f"(acc2), "+f"(acc3)                    \
            : "r"(aF[ks][0]), "r"(aF[ks][1]), "r"(aF[ks][2]), "r"(aF[ks][3]),   \
              "r"(rb0), "r"(rb1))
        SMMA(cA0, cA1, cA2, cA3, 0, Bv0.x, Bv0.y);
        SMMA(cA0, cA1, cA2, cA3, 2, Bv1.x, Bv1.y);
        SMMA(cA0, cA1, cA2, cA3, 4, Bv2.x, Bv2.y);
        SMMA(cA0, cA1, cA2, cA3, 6, Bv3.x, Bv3.y);
        SMMA(cB0, cB1, cB2, cB3, 1, Bv0.z, Bv0.w);
        SMMA(cB0, cB1, cB2, cB3, 3, Bv1.z, Bv1.w);
        SMMA(cB0, cB1, cB2, cB3, 5, Bv2.z, Bv2.w);
#undef SMMA
        float c0 = cA0 + cB0, c1 = cA1 + cB1;
        float c2 = cA2 + cB2, c3 = cA3 + cB3;
        // epilogue: every pt cell written exactly once across mt0/mt1 warps
        int j0 = nt * 8 + tig * 2;
        int2 kv0 = kb_s[j0];
        int2 kv1 = kb_s[j0 + 1];
        unsigned k0 = (unsigned)(ig ? kv0.y : kv0.x) >> (4 * gid);
        unsigned k1 = (unsigned)(ig ? kv1.y : kv1.x) >> (4 * gid);
        int iloc = ig * 8 + gid;
        float v0 = (c0 >= 0.f) ? c0 : 0.2f * c0;   // k = 2mt,   j0
        float v1 = (c1 >= 0.f) ? c1 : 0.2f * c1;   // k = 2mt,   j0+1
        float v2 = (c2 >= 0.f) ? c2 : 0.2f * c2;   // k = 2mt+1, j0
        float v3 = (c3 >= 0.f) ? c3 : 0.2f * c3;   // k = 2mt+1, j0+1
        unsigned kk0 = k0 & 3u, kk1 = k1 & 3u;
        bool val0 = (k0 & 4u) != 0, val1 = (k1 & 4u) != 0;
        if (mt == 0) {
            float r0 = !val0 ? NEGV : (kk0 == 0 ? v0 : v2);
            if (!val0 || kk0 <= 1) pt[j0 * PTS + iloc] = r0;
            float r1 = !val1 ? NEGV : (kk1 == 0 ? v1 : v3);
            if (!val1 || kk1 <= 1) pt[(j0 + 1) * PTS + iloc] = r1;
        } else {
            if (val0 && kk0 >= 2) pt[j0 * PTS + iloc]       = (kk0 == 2 ? v0 : v2);
            if (val1 && kk1 >= 2) pt[(j0 + 1) * PTS + iloc] = (kk1 == 2 ? v1 : v3);
        }
    }
    __syncthreads();

    // ---- softmax: warp w owns rows 2w and 2w+1 ----
#pragma unroll
    for (int r = 0; r < 2; ++r) {
        int irow = 2 * w + r;
        float al[7];
#pragma unroll
        for (int t = 0; t < 7; ++t) {
            int jj = lane + 32 * t;
            al[t] = (jj < NN) ? pt[jj * PTS + irow] : NEGV;
        }
        float m = al[0];
#pragma unroll
        for (int t = 1; t < 7; ++t) m = fmaxf(m, al[t]);
#pragma unroll
        for (int off = 16; off > 0; off >>= 1)
            m = fmaxf(m, __shfl_xor_sync(0xffffffffu, m, off));

        float pv[7];
        float sum = 0.f;
#pragma unroll
        for (int t = 0; t < 7; ++t) {
            int jj = lane + 32 * t;
            float e = (jj < NN) ? __expf(al[t] - m) : 0.f;
            pv[t] = e;
            sum += e;
        }
#pragma unroll
        for (int off = 16; off > 0; off >>= 1)
            sum += __shfl_xor_sync(0xffffffffu, sum, off);
        float rinv = 1.f / sum;
#pragma unroll
        for (int t = 0; t < 7; ++t) {
            int jj = lane + 32 * t;
            if (jj < NN) pp[irow * PPS + jj] = __float2half(pv[t] * rinv);
        }
    }
    __syncthreads();

    // ---- aggregation via HMMA: warps 0-3 -> i-group 0, warps 4-7 -> i-group 1 ----
    {
        const int aig = w >> 2;
        const int nt0 = w & 3;
        unsigned pA0[13], pA1[13];
#pragma unroll
        for (int kt = 0; kt < 13; ++kt) {
            pA0[kt] = *(const unsigned*)(pp + (aig * 8 + gid) * PPS + kt * 16 + tig * 2);
            pA1[kt] = *(const unsigned*)(pp + (aig * 8 + gid) * PPS + kt * 16 + tig * 2 + 8);
        }

        for (int nt = nt0; nt < 13; nt += 4) {
            // fragment-native B: 7 contiguous LDG.128 per job
            const __half* hb = hAgg_scratch + (((size_t)b * 13 + nt) * 7 * 32 + lane) * 8;
            unsigned hb0[13], hb1[13];
#pragma unroll
            for (int ktp = 0; ktp < 7; ++ktp) {
                uint4 v = *(const uint4*)(hb + (size_t)ktp * 32 * 8);
                hb0[2 * ktp] = v.x;
                hb1[2 * ktp] = v.y;
                if (ktp < 6) {
                    hb0[2 * ktp + 1] = v.z;
                    hb1[2 * ktp + 1] = v.w;
                }
            }
            float cA0 = 0.f, cA1 = 0.f, cA2 = 0.f, cA3 = 0.f;
            float cB0 = 0.f, cB1 = 0.f, cB2 = 0.f, cB3 = 0.f;
#pragma unroll
            for (int kt = 0; kt < 13; kt += 2) {
                asm("mma.sync.aligned.m16n8k16.row.col.f32.f16.f16.f32 "
                    "{%0,%1,%2,%3}, {%4,%5,%6,%7}, {%8,%9}, {%0,%1,%2,%3};"
                    : "+f"(cA0), "+f"(cA1), "+f"(cA2), "+f"(cA3)
                    : "r"(pA0[kt]), "r"(0u), "r"(pA1[kt]), "r"(0u),
                      "r"(hb0[kt]), "r"(hb1[kt]));
            }
#pragma unroll
            for (int kt = 1; kt < 13; kt += 2) {
                asm("mma.sync.aligned.m16n8k16.row.col.f32.f16.f16.f32 "
                    "{%0,%1,%2,%3}, {%4,%5,%6,%7}, {%8,%9}, {%0,%1,%2,%3};"
                    : "+f"(cB0), "+f"(cB1), "+f"(cB2), "+f"(cB3)
                    : "r"(pA0[kt]), "r"(0u), "r"(pA1[kt]), "r"(0u),
                      "r"(hb0[kt]), "r"(hb1[kt]));
            }
            int d0 = nt * 8 + tig * 2;
            int orow = i0 + aig * 8 + gid;
            if (d0 < DD && orow < NN) {
                float2 o;
                o.x = cA0 + cB0;
                o.y = cA1 + cB1;
                *(float2*)(out + (size_t)(b * NN + orow) * DD + d0) = o;
            }
        }
    }
}

extern "C" void kernel_launch(void* const* d_in, const int* in_sizes, int n_in,
                              void* d_out, int out_size)
{
    const int*   inputs = (const int*)d_in[0];
    const int*   adj    = (const int*)d_in[1];
    // d_in[2] = mask_item (unused by reference)
    const float* emb    = (const float*)d_in[3];
    const float* a0     = (const float*)d_in[4];
    const float* a1     = (const float*)d_in[5];
    const float* a2     = (const float*)d_in[6];
    const float* a3     = (const float*)d_in[7];
    float*       out    = (float*)d_out;

    cudaFuncSetAttribute(gnn_agg_kernel,
                         cudaFuncAttributeMaxDynamicSharedMemorySize,
                         SMEM_BYTES);

    // Phase 1: fused gather + fragment-native fp16 layouts (sBt, hAgg, ahq)
    dim3 pg(13, BB);     // 13 x 32 = 416 blocks (one per 16-j kt tile)
    prep_kernel<<<pg, 256>>>(inputs, emb, a0, a1, a2, a3);

    // Phase 2: fused HMMA-score / softmax / HMMA-aggregate
    dim3 grid((NN + IT - 1) / IT, BB);   // 13 x 32 = 416 blocks (~1 wave at 3/SM)
    gnn_agg_kernel<<<grid, 256, SMEM_BYTES>>>(adj, out);
}